// round 17
// baseline (speedup 1.0000x reference)
#include <cuda_runtime.h>
#include <stdint.h>

// Problem constants (fixed by the benchmark's setup_inputs)
namespace {
constexpr int BSZ     = 256;
constexpr int NMAX    = 8192;
constexpr int ENS     = 4;
constexpr int REPEAT  = 2;
constexpr int KSEL    = 32;
constexpr int ROWS    = REPEAT * BSZ * ENS;   // 2048
constexpr int T1      = 1024;                 // kernel-1 block
constexpr int EPT     = NMAX / T1;            // 8
constexpr float EPSF  = 1.17549435e-38f;      // np.float32 tiny
// State pre-scaled into log2 domain: y2 = f * (10/ln2), tau = 0.1.
constexpr float SCALE = 14.426950408889634f;  // 10 / ln(2)
// Validated participation cut (rel_err 0.0 rounds 13-16): elements > 30 log2
// below the current max contribute < 2^-30 and are negligible.
constexpr float HOT   = 30.0f;
constexpr float DT0   = 60.0f;   // initial candidate margin below m0
constexpr float DSTEP = 30.0f;   // build-retry threshold step
constexpr float DEXP  = 90.0f;   // expansion margin (guarantees loop exit)
constexpr int   MINC  = 48;      // minimum candidates before dynamics
constexpr int   CAP   = 1280;    // per-row candidate capacity (~5x expected)
constexpr int   W2    = 4;       // warps (rows) per kernel-2 block
// floats per warp region: cy2[CAP] + ckh[CAP] + u16 cidx[CAP] (=CAP/2 floats)
constexpr int   WSTRIDE = CAP * 2 + CAP / 2;
constexpr int   SMEM2   = W2 * WSTRIDE * 4;   // 51200 bytes
}

// global scratch (static device arrays: allocation-free per harness rules)
__device__ float g_y2[(size_t)ROWS * NMAX];   // initial y2 (rewritten each replay)
__device__ float g_kh[(size_t)ROWS * NMAX];   // khot scratch (fallback only)
__device__ float g_m0[ROWS];                  // per-row initial max

__device__ __forceinline__ float ex2_approx(float x) {
  float r; asm("ex2.approx.ftz.f32 %0, %1;" : "=f"(r) : "f"(x)); return r;
}
__device__ __forceinline__ float lg2_approx(float x) {
  float r; asm("lg2.approx.ftz.f32 %0, %1;" : "=f"(r) : "f"(x)); return r;
}
__device__ __forceinline__ float rcp_approx(float x) {
  float r; asm("rcp.approx.ftz.f32 %0, %1;" : "=f"(r) : "f"(x)); return r;
}

// order-preserving float<->uint mapping (REDUX-based float max)
__device__ __forceinline__ unsigned ford(float f) {
  unsigned u = __float_as_uint(f);
  return u ^ ((unsigned)((int)u >> 31) | 0x80000000u);
}
__device__ __forceinline__ float funord(unsigned e) {
  return __uint_as_float(e ^ ((~(unsigned)((int)e >> 31)) | 0x80000000u));
}

// JAX threefry2x32 with key = (0, 42)  (jax.random.key(42))
__device__ __forceinline__ void threefry2x32_0_42(uint32_t c0, uint32_t c1,
                                                  uint32_t& o0, uint32_t& o1) {
  const uint32_t k0 = 0u;
  const uint32_t k1 = 42u;
  const uint32_t k2 = 0x1BD11BDAu ^ k0 ^ k1;
  uint32_t x0 = c0 + k0;
  uint32_t x1 = c1 + k1;
#define TFR(r) { x0 += x1; x1 = __funnelshift_l(x1, x1, (r)); x1 ^= x0; }
  TFR(13) TFR(15) TFR(26) TFR(6)   x0 += k1; x1 += k2 + 1u;
  TFR(17) TFR(29) TFR(16) TFR(24)  x0 += k2; x1 += k0 + 2u;
  TFR(13) TFR(15) TFR(26) TFR(6)   x0 += k0; x1 += k1 + 3u;
  TFR(17) TFR(29) TFR(16) TFR(24)  x0 += k1; x1 += k2 + 4u;
  TFR(13) TFR(15) TFR(26) TFR(6)   x0 += k2; x1 += k0 + 5u;
#undef TFR
  o0 = x0; o1 = x1;
}

// ========================= kernel 1: wide init =============================
__global__ void __launch_bounds__(T1, 1)
k_init(const float* __restrict__ scores, float* __restrict__ out) {
  __shared__ unsigned shm[32];
  const int row  = blockIdx.x;
  const int t    = threadIdx.x;
  const int w    = t >> 5;
  const int lane = t & 31;
  const int rep  = row >> 10;
  const int q    = row & 1023;
  const int b    = q >> 2;
  const int e    = q & 3;

  const float* srow = scores + ((size_t)b * NMAX) * ENS + e;
  float* orow = out + (((size_t)(rep * BSZ + b)) * NMAX) * ENS + e;
  float* yr = g_y2 + (size_t)row * NMAX;

  float lm = -3.4e38f;
#pragma unroll
  for (int i = 0; i < EPT; i++) {
    const int n = t + i * T1;
    const unsigned j = (unsigned)row * (unsigned)NMAX + (unsigned)n;
    uint32_t r0, r1;
    threefry2x32_0_42(0u, j, r0, r1);           // partitionable: counter (0, j)
    const uint32_t bits = r0 ^ r1;
    float u = __uint_as_float((bits >> 9) | 0x3F800000u) - 1.0f;
    u = fmaxf(u + EPSF, EPSF);
    const float g = -logf(-logf(u));            // accurate path for init
    const float y = (srow[(size_t)n * ENS] + g) * SCALE;
    yr[n] = y;
    orow[(size_t)n * ENS] = 0.0f;               // clears poison
    lm = fmaxf(lm, y);
  }
  const unsigned o = __reduce_max_sync(0xFFFFFFFFu, ford(lm));
  if (lane == 0) shm[w] = o;
  __syncthreads();
  if (t < 32) {
    const unsigned v = __reduce_max_sync(0xFFFFFFFFu, shm[t]);
    if (t == 0) g_m0[row] = funord(v);
  }
}

// ================= kernel 2: one warp per row, full occupancy ==============
__global__ void __launch_bounds__(W2 * 32, 8)
k_dyn(float* __restrict__ out) {
  extern __shared__ float sm[];
  const int t    = threadIdx.x;
  const int w    = t >> 5;
  const int lane = t & 31;
  const unsigned lmlt = (lane == 0) ? 0u : (0xFFFFFFFFu >> (32 - lane));
  const int row  = blockIdx.x * W2 + w;
  const int rep  = row >> 10;
  const int q    = row & 1023;
  const int b    = q >> 2;
  const int e    = q & 3;

  float* cy2 = sm + w * WSTRIDE;               // [CAP]
  float* ckh = cy2 + CAP;                      // [CAP]
  unsigned short* cidx = (unsigned short*)(ckh + CAP);  // [CAP]

  const float* yr = g_y2 + (size_t)row * NMAX;
  float* orow = out + (((size_t)(rep * BSZ + b)) * NMAX) * ENS + e;
  const float m0 = g_m0[row];

  // ---- build candidate list {y2 >= T}, retry lower if too few ----
  float T = m0 - DT0;
  int cnt = 0;
  for (int tries = 0; tries < 8; tries++) {
    cnt = 0;
    for (int base = lane; base < NMAX; base += 32) {
      const float v = yr[base];
      const bool p = (v >= T);
      const unsigned mk = __ballot_sync(0xFFFFFFFFu, p);
      if (p) {
        const int r = cnt + __popc(mk & lmlt);
        if (r < CAP) { cy2[r] = v; ckh[r] = 0.0f; cidx[r] = (unsigned short)base; }
      }
      cnt += __popc(mk);
    }
    if (cnt >= MINC) break;
    T -= DSTEP;
  }
  __syncwarp();
  bool ok = (cnt <= CAP);

  // ---- 32 rounds over candidates ----
  if (ok) {
    for (int it = 0; it < KSEL; it++) {
      // candidate max with guaranteed coverage (expand at most once: after
      // expansion T = min(m2,T)-90 and new m2' >= m2, so m2'-30 >= T+60 > T)
      float m2;
      for (;;) {
        float lm2 = -3.4e38f;
        for (int c = lane; c < cnt; c += 32) lm2 = fmaxf(lm2, cy2[c]);
        m2 = funord(__reduce_max_sync(0xFFFFFFFFu, ford(lm2)));
        if (m2 - HOT >= T) break;
        const float Tn = fminf(m2, T) - DEXP;
        for (int base = lane; base < NMAX; base += 32) {
          const float v = yr[base];
          const bool p = (v >= Tn) && (v < T);   // window: no duplicates
          const unsigned mk = __ballot_sync(0xFFFFFFFFu, p);
          if (p) {
            const int r = cnt + __popc(mk & lmlt);
            if (r < CAP) { cy2[r] = v; ckh[r] = 0.0f; cidx[r] = (unsigned short)base; }
          }
          cnt += __popc(mk);
        }
        T = Tn;
        __syncwarp();
        if (cnt > CAP) { ok = false; break; }
      }
      if (!ok) break;

      // s = sum exp2(y2 - m2)   (ex2 underflow -> exact 0 for cold elements)
      float s = 0.0f;
      for (int c = lane; c < cnt; c += 32) s += ex2_approx(cy2[c] - m2);
#pragma unroll
      for (int o = 16; o; o >>= 1) s += __shfl_xor_sync(0xFFFFFFFFu, s, o);
      const float rs = rcp_approx(s);

      // khot += oh ; knock down winners
      for (int c = lane; c < cnt; c += 32) {
        const float y  = cy2[c];
        const float oh = ex2_approx(y - m2) * rs;
        ckh[c] += oh;                            // += 0 exact no-op when cold
        const float mkk = 1.0f - oh;
        if (mkk < 1.0f)                          // log(1)=0: exact skip
          cy2[c] = y + 10.0f * lg2_approx(fmaxf(mkk, EPSF));
      }
    }
  }

  // ---- fast top-k: exactly 32 khot > 0.5 => that IS the top-32 set ----
  if (ok) {
    int hi = 0;
    for (int c = lane; c < cnt; c += 32) hi += (ckh[c] > 0.5f) ? 1 : 0;
    hi = __reduce_add_sync(0xFFFFFFFFu, (unsigned)hi);
    if (hi == KSEL) {
      for (int c = lane; c < cnt; c += 32)
        if (ckh[c] > 0.5f) orow[(size_t)cidx[c] * ENS] = 1.0f;
      return;                                    // per-warp exit: no block syncs
    }
    ok = false;
  }

  // ============ fallback: full-row dynamics from pristine global y2 ========
  {
    float* y2r = g_y2 + (size_t)row * NMAX;      // safe to mutate: rewritten by
    float* khr = g_kh + (size_t)row * NMAX;      // kernel 1 on every replay
    for (int base = lane; base < NMAX; base += 32) khr[base] = 0.0f;
    __syncwarp();

    for (int it = 0; it < KSEL; it++) {
      float lm2 = -3.4e38f;
      for (int base = lane; base < NMAX; base += 32) lm2 = fmaxf(lm2, y2r[base]);
      const float m2 = funord(__reduce_max_sync(0xFFFFFFFFu, ford(lm2)));
      float s = 0.0f;
      for (int base = lane; base < NMAX; base += 32) s += ex2_approx(y2r[base] - m2);
#pragma unroll
      for (int o = 16; o; o >>= 1) s += __shfl_xor_sync(0xFFFFFFFFu, s, o);
      const float rs = rcp_approx(s);
      for (int base = lane; base < NMAX; base += 32) {
        const float y  = y2r[base];
        const float oh = ex2_approx(y - m2) * rs;
        khr[base] += oh;
        const float mkk = 1.0f - oh;
        if (mkk < 1.0f)
          y2r[base] = y + 10.0f * lg2_approx(fmaxf(mkk, EPSF));
      }
    }

    int hi = 0;
    for (int base = lane; base < NMAX; base += 32) hi += (khr[base] > 0.5f) ? 1 : 0;
    hi = __reduce_add_sync(0xFFFFFFFFu, (unsigned)hi);
    if (hi == KSEL) {
      for (int base = lane; base < NMAX; base += 32)
        if (khr[base] > 0.5f) orow[(size_t)base * ENS] = 1.0f;
      return;
    }

    // exact iterative argmax, lowest-index tie-break
    for (int sel = 0; sel < KSEL; sel++) {
      unsigned long long myk = 0ull;
      for (int base = lane; base < NMAX; base += 32) {
        const float kh = khr[base];
        const unsigned ord = (kh >= 0.0f)
            ? (__float_as_uint(kh) | 0x80000000u) : 0u;
        const unsigned long long key =
            ((unsigned long long)ord << 32) | (unsigned)(NMAX - 1 - base);
        myk = (key > myk) ? key : myk;
      }
      const unsigned mh = __reduce_max_sync(0xFFFFFFFFu, (unsigned)(myk >> 32));
      const unsigned ml = __reduce_max_sync(
          0xFFFFFFFFu, ((unsigned)(myk >> 32) == mh) ? (unsigned)myk : 0u);
      const int n = NMAX - 1 - (int)ml;
      if (lane == (n & 31)) {                    // owner lane (base ≡ lane mod 32)
        khr[n] = -1.0f;
        orow[(size_t)n * ENS] = 1.0f;
      }
      __syncwarp();
    }
  }
}

extern "C" void kernel_launch(void* const* d_in, const int* in_sizes, int n_in,
                              void* d_out, int out_size) {
  const float* scores = (const float*)d_in[0];
  float* out = (float*)d_out;
  cudaFuncSetAttribute(k_dyn, cudaFuncAttributeMaxDynamicSharedMemorySize, SMEM2);
  k_init<<<ROWS, T1>>>(scores, out);
  k_dyn<<<ROWS / W2, W2 * 32, SMEM2>>>(out);
  (void)in_sizes; (void)n_in; (void)out_size;
}